// round 11
// baseline (speedup 1.0000x reference)
#include <cuda_runtime.h>
#include <cuda_bf16.h>

// Problem constants: B=32, T=1024, F=4, C=256, S=256, MAX_DUR=8 (durations <= 7)
#define BQ 32
#define TQ 1024
#define FQ 4
#define CQ 256
#define SQ 256

// ---------------------------------------------------------------------------
// Single fused kernel. Grid: 8192 blocks = one per (batch, segment), 256 thr.
// Phase 1: inclusive scan of this batch's 256 durations (redundant across the
// 256 blocks of a batch; the 1-2 KB duration row is L1/L2-hot after first
// touch, and the prologue overlaps across ~7 resident blocks/SM).
// Phase 2 (R8 shape, best measured): thread = channel c; accumulate over the
// segment's cnt frames x 4 freq bins with fully-coalesced scalar loads
// (4 independent LDGs per frame iteration). Coalesced scalar store.
//
// Dtype: reference declares int64 but JAX w/o x64 downcasts to int32; detect
// on device via high words (all zero <=> int64; P(false pos)=8^-32).
// ---------------------------------------------------------------------------
__global__ __launch_bounds__(256, 7) void fused_kernel(const float* __restrict__ e,
                                                       const int* __restrict__ dur_raw,
                                                       float* __restrict__ out) {
    __shared__ int sh_cum[SQ];
    __shared__ int warp_tot[8];
    __shared__ int s_is64;

    const int blk = blockIdx.x;
    const int b   = blk >> 8;          // batch
    const int s   = blk & (SQ - 1);    // segment
    const int tid = threadIdx.x;
    const int lane = tid & 31;
    const int w    = tid >> 5;

    // --- dtype probe (first 32 candidate int64 high words of whole array) ---
    if (tid < 32) {
        int v = dur_raw[2 * tid + 1];
        unsigned m = __ballot_sync(0xffffffffu, v != 0);
        if (tid == 0) s_is64 = (m == 0u) ? 1 : 0;
    }
    __syncthreads();

    // --- phase 1: inclusive scan of batch b's durations (tid = phone id) ---
    int d = s_is64 ? dur_raw[(b * SQ + tid) * 2]    // low word of LE int64
                   : dur_raw[b * SQ + tid];

    int x = d;
    #pragma unroll
    for (int off = 1; off < 32; off <<= 1) {
        int y = __shfl_up_sync(0xffffffffu, x, off);
        if (lane >= off) x += y;
    }
    if (lane == 31) warp_tot[w] = x;
    __syncthreads();

    int base = 0;
    #pragma unroll
    for (int i = 0; i < 8; ++i)
        if (i < w) base += warp_tot[i];

    sh_cum[tid] = base + x;
    __syncthreads();

    // --- phase 2: this block's segment; thread tid = channel c ---
    const int incl  = sh_cum[s];
    const int excl  = (s == 0) ? 0 : sh_cum[s - 1];
    const int start = min(excl, TQ);
    const int cnt   = min(incl, TQ) - start;

    float acc = 0.0f;
    if (cnt > 0) {
        const float* p = e + (size_t)(b * TQ + start) * (FQ * CQ) + tid;
        for (int t = 0; t < cnt; ++t) {
            float a0 = p[0];
            float a1 = p[CQ];
            float a2 = p[2 * CQ];
            float a3 = p[3 * CQ];
            acc += (a0 + a1) + (a2 + a3);
            p += FQ * CQ;
        }
        acc *= 1.0f / (float)(cnt * FQ);
    }
    out[(size_t)blk * CQ + tid] = acc;
}

extern "C" void kernel_launch(void* const* d_in, const int* in_sizes, int n_in,
                              void* d_out, int out_size) {
    const float* e_src = (const float*)d_in[0];   // [B, T, F, C] float32
    const int*   d_src = (const int*)d_in[1];     // [B, S] int64-or-int32 (detected)
    float* out = (float*)d_out;                   // [B, S, C] float32

    fused_kernel<<<BQ * SQ, 256>>>(e_src, d_src, out);
}

// round 12
// speedup vs baseline: 1.1189x; 1.1189x over previous
#include <cuda_runtime.h>
#include <cuda_bf16.h>

// Problem constants: B=32, T=1024, F=4, C=256, S=256, MAX_DUR=8 (durations <= 7)
#define BQ 32
#define TQ 1024
#define FQ 4
#define CQ 256
#define SQ 256
#define ROW_VEC 256   // one frame row [F=4][C=256] = 1024 floats = 256 float4

// ---------------------------------------------------------------------------
// Single fused kernel, R8 phase-2 body (best measured: 23.5us, DRAM 66%).
// Grid: 8192 blocks = one per (batch, segment), 256 threads.
// Phase 1: in-block inclusive scan of the batch's 256 durations (dur row is
// 1-2 KB, L1/L2-hot after the first blocks of each batch touch it).
// Phase 2: thread tid loads float4 #tid of each frame row (a row is exactly
// 256 float4 spanning all F and C); frame loop unrolled to 8 predicated
// iterations -> 8 independent LDG.128 in flight. Freq reduce via one smem
// pass; coalesced float4 store by 64 threads.
//
// Dtype: reference declares int64 but JAX w/o x64 downcasts to int32; detect
// on device via high words (all zero <=> int64; P(false pos)=8^-32).
// ---------------------------------------------------------------------------
__global__ __launch_bounds__(256, 7) void fused_kernel(const float4* __restrict__ e4,
                                                       const int* __restrict__ dur_raw,
                                                       float4* __restrict__ out4) {
    __shared__ int sh_cum[SQ];
    __shared__ int warp_tot[8];
    __shared__ int s_is64;
    __shared__ float4 sh[CQ];

    const int blk = blockIdx.x;
    const int b   = blk >> 8;          // batch
    const int s   = blk & (SQ - 1);    // segment
    const int tid = threadIdx.x;
    const int lane = tid & 31;
    const int w    = tid >> 5;

    // --- dtype probe (first 32 candidate int64 high words of whole array) ---
    if (tid < 32) {
        int v = dur_raw[2 * tid + 1];
        unsigned m = __ballot_sync(0xffffffffu, v != 0);
        if (tid == 0) s_is64 = (m == 0u) ? 1 : 0;
    }
    __syncthreads();

    // --- phase 1: inclusive scan of batch b's durations (tid = phone id) ---
    int d = s_is64 ? dur_raw[(b * SQ + tid) * 2]    // low word of LE int64
                   : dur_raw[b * SQ + tid];

    int x = d;
    #pragma unroll
    for (int off = 1; off < 32; off <<= 1) {
        int y = __shfl_up_sync(0xffffffffu, x, off);
        if (lane >= off) x += y;
    }
    if (lane == 31) warp_tot[w] = x;
    __syncthreads();

    int base = 0;
    #pragma unroll
    for (int i = 0; i < 8; ++i)
        if (i < w) base += warp_tot[i];

    sh_cum[tid] = base + x;
    __syncthreads();

    // --- phase 2 (R8 body): this block's segment ---
    const int incl  = sh_cum[s];
    const int excl  = (s == 0) ? 0 : sh_cum[s - 1];
    const int start = min(excl, TQ);
    const int cnt   = min(incl, TQ) - start;

    const float4* p = e4 + (size_t)(b * TQ + start) * ROW_VEC + tid;

    float4 acc = make_float4(0.f, 0.f, 0.f, 0.f);
    #pragma unroll
    for (int t = 0; t < 8; ++t) {
        if (t < cnt) {
            float4 v = p[t * ROW_VEC];
            acc.x += v.x; acc.y += v.y; acc.z += v.z; acc.w += v.w;
        }
    }
    sh[tid] = acc;
    __syncthreads();

    if (tid < 64) {
        float4 a  = sh[tid];
        float4 b1 = sh[tid + 64];
        float4 b2 = sh[tid + 128];
        float4 b3 = sh[tid + 192];
        const float inv = (cnt > 0) ? 1.0f / (float)(cnt * FQ) : 0.0f;
        float4 r;
        r.x = ((a.x + b1.x) + (b2.x + b3.x)) * inv;
        r.y = ((a.y + b1.y) + (b2.y + b3.y)) * inv;
        r.z = ((a.z + b1.z) + (b2.z + b3.z)) * inv;
        r.w = ((a.w + b1.w) + (b2.w + b3.w)) * inv;
        out4[(size_t)blk * 64 + tid] = r;
    }
}

extern "C" void kernel_launch(void* const* d_in, const int* in_sizes, int n_in,
                              void* d_out, int out_size) {
    const float4* e_src = (const float4*)d_in[0];   // [B, T, F, C] float32
    const int*    d_src = (const int*)d_in[1];      // [B, S] int64-or-int32 (detected)
    float4* out = (float4*)d_out;                   // [B, S, C] float32

    fused_kernel<<<BQ * SQ, 256>>>(e_src, d_src, out);
}

// round 14
// speedup vs baseline: 1.1620x; 1.0385x over previous
#include <cuda_runtime.h>
#include <cuda_bf16.h>

// Problem constants: B=32, T=1024, F=4, C=256, S=256, MAX_DUR=8 (durations <= 7)
#define BQ 32
#define TQ 1024
#define FQ 4
#define CQ 256
#define SQ 256
#define ROW_VEC 256   // one frame row [F=4][C=256] = 1024 floats = 256 float4

// ---------------------------------------------------------------------------
// Single fused kernel (R12 winner) + streaming cache hints on the e stream.
// Grid: 8192 blocks = one per (batch, segment), 256 threads.
// Phase 1: in-block inclusive scan of the batch's 256 durations.
// Phase 2: thread tid loads float4 #tid of each frame row via __ldcs
// (read-once, evict-first); 8 predicated unrolled frames -> MLP 8. Freq
// reduce via one smem pass; coalesced float4 __stcs store by 64 threads.
//
// Dtype: reference declares int64 but JAX w/o x64 downcasts to int32; detect
// on device via high words (all zero <=> int64; P(false pos)=8^-32).
// ---------------------------------------------------------------------------
__global__ __launch_bounds__(256, 7) void fused_kernel(const float4* __restrict__ e4,
                                                       const int* __restrict__ dur_raw,
                                                       float4* __restrict__ out4) {
    __shared__ int sh_cum[SQ];
    __shared__ int warp_tot[8];
    __shared__ int s_is64;
    __shared__ float4 sh[CQ];

    const int blk = blockIdx.x;
    const int b   = blk >> 8;          // batch
    const int s   = blk & (SQ - 1);    // segment
    const int tid = threadIdx.x;
    const int lane = tid & 31;
    const int w    = tid >> 5;

    // --- dtype probe (first 32 candidate int64 high words of whole array) ---
    if (tid < 32) {
        int v = dur_raw[2 * tid + 1];
        unsigned m = __ballot_sync(0xffffffffu, v != 0);
        if (tid == 0) s_is64 = (m == 0u) ? 1 : 0;
    }
    __syncthreads();

    // --- phase 1: inclusive scan of batch b's durations (tid = phone id) ---
    int d = s_is64 ? dur_raw[(b * SQ + tid) * 2]    // low word of LE int64
                   : dur_raw[b * SQ + tid];

    int x = d;
    #pragma unroll
    for (int off = 1; off < 32; off <<= 1) {
        int y = __shfl_up_sync(0xffffffffu, x, off);
        if (lane >= off) x += y;
    }
    if (lane == 31) warp_tot[w] = x;
    __syncthreads();

    int base = 0;
    #pragma unroll
    for (int i = 0; i < 8; ++i)
        if (i < w) base += warp_tot[i];

    sh_cum[tid] = base + x;
    __syncthreads();

    // --- phase 2 (R8 body + .cs hints): this block's segment ---
    const int incl  = sh_cum[s];
    const int excl  = (s == 0) ? 0 : sh_cum[s - 1];
    const int start = min(excl, TQ);
    const int cnt   = min(incl, TQ) - start;

    const float4* p = e4 + (size_t)(b * TQ + start) * ROW_VEC + tid;

    float4 acc = make_float4(0.f, 0.f, 0.f, 0.f);
    #pragma unroll
    for (int t = 0; t < 8; ++t) {
        if (t < cnt) {
            float4 v = __ldcs(p + t * ROW_VEC);   // read-once: evict-first
            acc.x += v.x; acc.y += v.y; acc.z += v.z; acc.w += v.w;
        }
    }
    sh[tid] = acc;
    __syncthreads();

    if (tid < 64) {
        float4 a  = sh[tid];
        float4 b1 = sh[tid + 64];
        float4 b2 = sh[tid + 128];
        float4 b3 = sh[tid + 192];
        const float inv = (cnt > 0) ? 1.0f / (float)(cnt * FQ) : 0.0f;
        float4 r;
        r.x = ((a.x + b1.x) + (b2.x + b3.x)) * inv;
        r.y = ((a.y + b1.y) + (b2.y + b3.y)) * inv;
        r.z = ((a.z + b1.z) + (b2.z + b3.z)) * inv;
        r.w = ((a.w + b1.w) + (b2.w + b3.w)) * inv;
        __stcs(out4 + (size_t)blk * 64 + tid, r); // write-once: evict-first
    }
}

extern "C" void kernel_launch(void* const* d_in, const int* in_sizes, int n_in,
                              void* d_out, int out_size) {
    const float4* e_src = (const float4*)d_in[0];   // [B, T, F, C] float32
    const int*    d_src = (const int*)d_in[1];      // [B, S] int64-or-int32 (detected)
    float4* out = (float4*)d_out;                   // [B, S, C] float32

    fused_kernel<<<BQ * SQ, 256>>>(e_src, d_src, out);
}